// round 14
// baseline (speedup 1.0000x reference)
#include <cuda_runtime.h>
#include <cuda_fp16.h>
#include <math_constants.h>
#include <cstdint>

// ----------------------------------------------------------------------------
// Window VQ via mma.sync fp16 tensor cores (base ISA, works on sm_100 target).
//   argmin_k ||z - c_k||^2 == argmax_k ( z.c_k - 0.5*||c_k||^2 )
// fp32 emulated as 2-way fp16 split: x = x1 + x2/2048, x2 stored pre-scaled
// by 2^11. 3 passes {11 -> accM; 21, 12 -> accR}, score = accM + accR*2^-11.
//
// R14 = R13 minus non-MMA overhead:
//  - BOTH A split images register-resident (a1f + a2f): in-loop LDSM is
//    B-only (32/tile/warp vs 48)
//  - 1 CTA/SM (no reg cap; R12 showed 2 CTA/SM worth ~1%)
//  - triple-buffered B with cp.async wait_group 1 (staging latency hidden)
// ----------------------------------------------------------------------------

#define D       128
#define BMW     64      // windows per CTA
#define NTE     64      // codebook entries per staged tile
#define NTHR    256

#define RSCALE  4.8828125e-4f   // 2^-11

// smem byte offsets: A 32KB | B 3x32KB | cnorm 8KB = 136KB
#define OFF_A    0
#define OFF_B    32768
#define OFF_CN   131072
#define SMEM_TOTAL 139264

__device__ float g_cnorm[4096];
// packed B splits: [nt 0..31][s 0..1][j 0..7][kt 0..15][r 0..7][c 0..7] fp16, 1MB
__device__ __align__(16) __half g_Bpk[32 * 2 * 8 * 16 * 64];

// ---------------------------------------------------------------------------
__global__ void cnorm_kernel(const float* __restrict__ cb, int K) {
    int row  = blockIdx.x * 8 + (threadIdx.x >> 5);
    int lane = threadIdx.x & 31;
    if (row < K) {
        const float4 v = reinterpret_cast<const float4*>(cb + (size_t)row * D)[lane];
        float s = v.x * v.x + v.y * v.y + v.z * v.z + v.w * v.w;
        #pragma unroll
        for (int o = 16; o; o >>= 1) s += __shfl_xor_sync(0xffffffffu, s, o);
        if (lane == 0) g_cnorm[row] = 0.5f * s;
    }
}

__device__ __forceinline__ void split2(float x, __half& h1, __half& h2) {
    h1 = __float2half_rn(x);
    h2 = __float2half_rn((x - __half2float(h1)) * 2048.0f);   // scaled residual
}

// Pack codebook: entry n, dim k -> per (nt=n/64, split, j=(n/8)%8, kt=k/8):
// 8x8 fp16 tile (row r = n%8, col c = k%8) stored as 128B contiguous.
__global__ void pack_cb_kernel(const float* __restrict__ cb, int K) {
    const int idx = blockIdx.x * NTHR + threadIdx.x;
    if (idx >= K * D) return;
    const int n = idx >> 7, k = idx & 127;
    __half h1, h2;
    split2(cb[idx], h1, h2);
    const int nt = n >> 6, j = (n >> 3) & 7, r = n & 7;
    const int kt = k >> 3, c = k & 7;
    const size_t off = (size_t)nt * 16384 + j * 1024 + kt * 64 + r * 8 + c;
    g_Bpk[off]        = h1;
    g_Bpk[off + 8192] = h2;
}

// ---------------------------------------------------------------------------
#define LDSM4(r0, r1, r2, r3, a) \
    asm volatile("ldmatrix.sync.aligned.m8n8.x4.shared.b16 {%0,%1,%2,%3}, [%4];" \
                 : "=r"(r0), "=r"(r1), "=r"(r2), "=r"(r3) : "r"(a))

#define MMA(ac, A0, A1, A2, A3, B0, B1) \
    asm volatile("mma.sync.aligned.m16n8k16.row.col.f32.f16.f16.f32 " \
                 "{%0,%1,%2,%3},{%4,%5,%6,%7},{%8,%9},{%0,%1,%2,%3};" \
                 : "+f"(ac[0]), "+f"(ac[1]), "+f"(ac[2]), "+f"(ac[3]) \
                 : "r"(A0), "r"(A1), "r"(A2), "r"(A3), "r"(B0), "r"(B1))

__device__ __forceinline__ uint32_t smem_u32(const void* p) {
    uint32_t a;
    asm("{ .reg .u64 t; cvta.to.shared.u64 t, %1; cvt.u32.u64 %0, t; }" : "=r"(a) : "l"(p));
    return a;
}
__device__ __forceinline__ void cp_async16(uint32_t saddr, const void* g) {
    asm volatile("cp.async.cg.shared.global [%0], [%1], 16;" :: "r"(saddr), "l"(g));
}

// load 8 k-step B fragments (16 regs) for one n8 region (2KB of tiles).
// addr MUST already include lane*16 (per-lane row address for ldmatrix).
__device__ __forceinline__ void load_bfrags(uint32_t* b, uint32_t addr) {
    #pragma unroll
    for (int q = 0; q < 4; ++q)
        LDSM4(b[q * 4 + 0], b[q * 4 + 1], b[q * 4 + 2], b[q * 4 + 3], addr + q * 512);
}

// pass with register-resident A fragments
__device__ __forceinline__ void mma_pass(float (*acc)[4], const uint32_t (*af)[4],
                                         const uint32_t* b0, const uint32_t* b1) {
    #pragma unroll
    for (int kk = 0; kk < 8; ++kk) {
        MMA(acc[0], af[kk][0], af[kk][1], af[kk][2], af[kk][3], b0[2 * kk], b0[2 * kk + 1]);
        MMA(acc[1], af[kk][0], af[kk][1], af[kk][2], af[kk][3], b1[2 * kk], b1[2 * kk + 1]);
    }
}

// ---------------------------------------------------------------------------
// Warp w: m-tile = w&3 (rows 16*(w&3)..+15), n-half = w>>2 (n8 groups
// 4*(w>>2) + {0..3} of the 8 groups in each 64-entry staged tile).
// ---------------------------------------------------------------------------
__global__ __launch_bounds__(NTHR, 1)
void vq_mma_kernel(const float* __restrict__ ze,
                   const float* __restrict__ cb,
                   float* __restrict__ out,
                   int ntiles) {
    extern __shared__ __align__(16) char smem[];
    float* Cn = reinterpret_cast<float*>(smem + OFF_CN);

    const uint32_t sbase = smem_u32(smem);
    const int tid  = threadIdx.x;
    const int w    = tid >> 5;
    const int lane = tid & 31;

    // ---- 1. build A split tiles in smem (ldmatrix-packed, mma subtile order) ----
    {
        const float* zsrc = ze + (size_t)blockIdx.x * (BMW * D);
        for (int i = tid; i < BMW * D; i += NTHR) {
            const int m = i >> 7, k = i & 127;
            __half h1, h2;
            split2(zsrc[i], h1, h2);
            const int t = ((m >> 3) & 1) | (((k >> 3) & 1) << 1);
            const int base = (m >> 4) * 4096 + (k >> 4) * 512 + t * 128
                           + (m & 7) * 16 + (k & 7) * 2;
            *reinterpret_cast<__half*>(smem + base)         = h1;
            *reinterpret_cast<__half*>(smem + base + 16384) = h2;
        }
        for (int i = tid; i < ntiles * NTE; i += NTHR) Cn[i] = g_cnorm[i];
    }

    // ---- 2. prologue: stage B tiles 0 and 1 (32KB each) ----
    #pragma unroll
    for (int c0 = 0; c0 < 2; ++c0) {
        const char* src = reinterpret_cast<const char*>(g_Bpk) + (size_t)c0 * 32768;
        const uint32_t dst = sbase + OFF_B + (uint32_t)c0 * 32768u;
        #pragma unroll
        for (int u = 0; u < 8; ++u)
            cp_async16(dst + u * 4096 + tid * 16, src + u * 4096 + tid * 16);
        asm volatile("cp.async.commit_group;");
    }
    __syncthreads();   // A tiles visible to all warps

    // ---- 3. BOTH A split fragment sets resident in registers (m-tile = w&3) ----
    uint32_t a1f[8][4], a2f[8][4];
    const uint32_t abase = sbase + (w & 3) * 4096 + lane * 16;
    #pragma unroll
    for (int kk = 0; kk < 8; ++kk)
        LDSM4(a1f[kk][0], a1f[kk][1], a1f[kk][2], a1f[kk][3], abase + kk * 512);
    #pragma unroll
    for (int kk = 0; kk < 8; ++kk)
        LDSM4(a2f[kk][0], a2f[kk][1], a2f[kk][2], a2f[kk][3], abase + 16384 + kk * 512);

    float best[2] = {-CUDART_INF_F, -CUDART_INF_F};
    int   bidx[2] = {0, 0};

    for (int nt = 0; nt < ntiles; ++nt) {
        if (nt + 1 < ntiles) asm volatile("cp.async.wait_group 1;");
        else                 asm volatile("cp.async.wait_group 0;");
        __syncthreads();   // buf[nt%3] full for all; compute nt-1 done everywhere

        // issue tile nt+2 into buf[(nt+2)%3] (last read during compute nt-1)
        if (nt + 2 < ntiles) {
            const char* src = reinterpret_cast<const char*>(g_Bpk) + (size_t)(nt + 2) * 32768;
            const uint32_t dst = sbase + OFF_B + (uint32_t)((nt + 2) % 3) * 32768u;
            #pragma unroll
            for (int u = 0; u < 8; ++u)
                cp_async16(dst + u * 4096 + tid * 16, src + u * 4096 + tid * 16);
            asm volatile("cp.async.commit_group;");
        }

        // per-lane base inside the current B buffer
        const uint32_t bb = sbase + OFF_B + (uint32_t)(nt % 3) * 32768u + lane * 16;
        const int ntbase = nt * NTE;

        #pragma unroll
        for (int jj = 0; jj < 2; ++jj) {
            const int g0 = (w >> 2) * 4 + 2 * jj;         // first n8 group
            float accM[2][4] = {{0.f, 0.f, 0.f, 0.f}, {0.f, 0.f, 0.f, 0.f}};
            float accR[2][4] = {{0.f, 0.f, 0.f, 0.f}, {0.f, 0.f, 0.f, 0.f}};
            uint32_t b0r[16], b1r[16];

            // split s=0 of B (B1): passes (A1,B1)->accM, (A2',B1)->accR
            load_bfrags(b0r, bb + g0 * 2048);
            load_bfrags(b1r, bb + (g0 + 1) * 2048);
            mma_pass(accM, a1f, b0r, b1r);
            mma_pass(accR, a2f, b0r, b1r);

            // split s=1 of B (B2'): pass (A1,B2')->accR
            load_bfrags(b0r, bb + 16384 + g0 * 2048);
            load_bfrags(b1r, bb + 16384 + (g0 + 1) * 2048);
            mma_pass(accR, a1f, b0r, b1r);

            // ---- epilogue: score = accM + accR*2^-11 - cn, running argmax ----
            #pragma unroll
            for (int js = 0; js < 2; ++js) {
                const int n0 = ntbase + (g0 + js) * 8 + 2 * (lane & 3);
                const float2 cn2 = *reinterpret_cast<const float2*>(&Cn[n0]);
                const float s00 = fmaf(accR[js][0], RSCALE, accM[js][0]) - cn2.x;
                const float s01 = fmaf(accR[js][1], RSCALE, accM[js][1]) - cn2.y;
                const float s10 = fmaf(accR[js][2], RSCALE, accM[js][2]) - cn2.x;
                const float s11 = fmaf(accR[js][3], RSCALE, accM[js][3]) - cn2.y;
                if (s00 > best[0]) { best[0] = s00; bidx[0] = n0; }
                if (s01 > best[0]) { best[0] = s01; bidx[0] = n0 + 1; }
                if (s10 > best[1]) { best[1] = s10; bidx[1] = n0; }
                if (s11 > best[1]) { best[1] = s11; bidx[1] = n0 + 1; }
            }
        }
    }

    // ---- reduce 8 candidates per window (4 lane-quads x 2 n-halves) ----
    float* sF   = reinterpret_cast<float*>(smem + OFF_B);          // [64][8]
    int*   sI   = reinterpret_cast<int*>(smem + OFF_B + 2048);
    int*   widx = reinterpret_cast<int*>(smem + OFF_B + 4096);
    __syncthreads();      // all warps done reading B buffers
    {
        const int m0  = 16 * (w & 3) + (lane >> 2);
        const int col = (w >> 2) * 4 + (lane & 3);
        sF[m0 * 8 + col] = best[0];        sI[m0 * 8 + col] = bidx[0];
        sF[(m0 + 8) * 8 + col] = best[1];  sI[(m0 + 8) * 8 + col] = bidx[1];
    }
    __syncthreads();
    if (tid < BMW) {
        float bs = sF[tid * 8];
        int   bi = sI[tid * 8];
        #pragma unroll
        for (int q = 1; q < 8; ++q) {
            const float s  = sF[tid * 8 + q];
            const int   ix = sI[tid * 8 + q];
            if (s > bs || (s == bs && ix < bi)) { bs = s; bi = ix; }
        }
        widx[tid] = bi;
    }
    __syncthreads();

    // ---- gather winning codebook rows (L2-hot) ----
    const float4* cb4  = reinterpret_cast<const float4*>(cb);
    float4*       out4 = reinterpret_cast<float4*>(out) + (size_t)blockIdx.x * (BMW * 32);
    #pragma unroll
    for (int i = 0; i < 8; ++i) {
        const int f = i * 256 + tid;          // 0..2047
        const int wv = f >> 5, c = f & 31;
        out4[f] = __ldg(&cb4[(size_t)widx[wv] * 32 + c]);
    }
}

// ---------------------------------------------------------------------------
extern "C" void kernel_launch(void* const* d_in, const int* in_sizes, int n_in,
                              void* d_out, int out_size) {
    const float* ze = (const float*)d_in[0];
    const float* cb = (const float*)d_in[1];
    float* out = (float*)d_out;

    const int M = in_sizes[0] / D;   // 65536
    const int K = in_sizes[1] / D;   // 2048

    cudaFuncSetAttribute(vq_mma_kernel, cudaFuncAttributeMaxDynamicSharedMemorySize,
                         SMEM_TOTAL);

    cnorm_kernel<<<(K + 7) / 8, NTHR>>>(cb, K);
    pack_cb_kernel<<<(K * D + NTHR - 1) / NTHR, NTHR>>>(cb, K);
    vq_mma_kernel<<<M / BMW, NTHR, SMEM_TOTAL>>>(ze, cb, out, K / NTE);
}

// round 15
// speedup vs baseline: 1.1697x; 1.1697x over previous
#include <cuda_runtime.h>
#include <cuda_fp16.h>
#include <math_constants.h>
#include <cstdint>

// ----------------------------------------------------------------------------
// Window VQ via mma.sync fp16 tensor cores (base ISA, works on sm_100 target).
//   argmin_k ||z - c_k||^2 == argmax_k ( z.c_k - 0.5*||c_k||^2 )
// fp32 emulated as 2-way fp16 split: x = x1 + x2/2048, x2 stored pre-scaled
// by 2^11. 3 passes {11 -> accM; 21, 12 -> accR}, score = accM + accR*2^-11.
//
// R15 = R13 with A-LDSM removed WHILE KEEPING 2 CTAs/SM:
//  - both A split images register-resident (64 regs)
//  - warp's 4 n8-groups processed sequentially with ONE 16-reg B set
//    -> ~110 regs total, fits the 128 cap without spilling
//  - in-loop LDSM 48 -> 32 per warp per tile (B-only, irreducible)
// ----------------------------------------------------------------------------

#define D       128
#define BMW     64      // windows per CTA
#define NTE     64      // codebook entries per staged tile
#define NTHR    256

#define RSCALE  4.8828125e-4f   // 2^-11

// smem byte offsets: A 32KB | B0 32KB | B1 32KB | cnorm 8KB = 104KB
#define OFF_A    0
#define OFF_B0   32768
#define OFF_B1   65536
#define OFF_CN   98304
#define SMEM_TOTAL 106496

__device__ float g_cnorm[4096];
// packed B splits: [nt 0..31][s 0..1][j 0..7][kt 0..15][r 0..7][c 0..7] fp16, 1MB
__device__ __align__(16) __half g_Bpk[32 * 2 * 8 * 16 * 64];

// ---------------------------------------------------------------------------
__global__ void cnorm_kernel(const float* __restrict__ cb, int K) {
    int row  = blockIdx.x * 8 + (threadIdx.x >> 5);
    int lane = threadIdx.x & 31;
    if (row < K) {
        const float4 v = reinterpret_cast<const float4*>(cb + (size_t)row * D)[lane];
        float s = v.x * v.x + v.y * v.y + v.z * v.z + v.w * v.w;
        #pragma unroll
        for (int o = 16; o; o >>= 1) s += __shfl_xor_sync(0xffffffffu, s, o);
        if (lane == 0) g_cnorm[row] = 0.5f * s;
    }
}

__device__ __forceinline__ void split2(float x, __half& h1, __half& h2) {
    h1 = __float2half_rn(x);
    h2 = __float2half_rn((x - __half2float(h1)) * 2048.0f);   // scaled residual
}

// Pack codebook: entry n, dim k -> per (nt=n/64, split, j=(n/8)%8, kt=k/8):
// 8x8 fp16 tile (row r = n%8, col c = k%8) stored as 128B contiguous.
__global__ void pack_cb_kernel(const float* __restrict__ cb, int K) {
    const int idx = blockIdx.x * NTHR + threadIdx.x;
    if (idx >= K * D) return;
    const int n = idx >> 7, k = idx & 127;
    __half h1, h2;
    split2(cb[idx], h1, h2);
    const int nt = n >> 6, j = (n >> 3) & 7, r = n & 7;
    const int kt = k >> 3, c = k & 7;
    const size_t off = (size_t)nt * 16384 + j * 1024 + kt * 64 + r * 8 + c;
    g_Bpk[off]        = h1;
    g_Bpk[off + 8192] = h2;
}

// ---------------------------------------------------------------------------
#define LDSM4(r0, r1, r2, r3, a) \
    asm volatile("ldmatrix.sync.aligned.m8n8.x4.shared.b16 {%0,%1,%2,%3}, [%4];" \
                 : "=r"(r0), "=r"(r1), "=r"(r2), "=r"(r3) : "r"(a))

#define MMA(ac, A0, A1, A2, A3, B0, B1) \
    asm volatile("mma.sync.aligned.m16n8k16.row.col.f32.f16.f16.f32 " \
                 "{%0,%1,%2,%3},{%4,%5,%6,%7},{%8,%9},{%0,%1,%2,%3};" \
                 : "+f"(ac[0]), "+f"(ac[1]), "+f"(ac[2]), "+f"(ac[3]) \
                 : "r"(A0), "r"(A1), "r"(A2), "r"(A3), "r"(B0), "r"(B1))

__device__ __forceinline__ uint32_t smem_u32(const void* p) {
    uint32_t a;
    asm("{ .reg .u64 t; cvta.to.shared.u64 t, %1; cvt.u32.u64 %0, t; }" : "=r"(a) : "l"(p));
    return a;
}
__device__ __forceinline__ void cp_async16(uint32_t saddr, const void* g) {
    asm volatile("cp.async.cg.shared.global [%0], [%1], 16;" :: "r"(saddr), "l"(g));
}

// load 8 k-step B fragments (16 regs) for one n8 region (2KB of tiles).
// addr MUST already include lane*16 (per-lane row address for ldmatrix).
__device__ __forceinline__ void load_bfrags(uint32_t* b, uint32_t addr) {
    #pragma unroll
    for (int q = 0; q < 4; ++q)
        LDSM4(b[q * 4 + 0], b[q * 4 + 1], b[q * 4 + 2], b[q * 4 + 3], addr + q * 512);
}

// single-group pass: 8 k-steps into one accumulator set
__device__ __forceinline__ void mma_pass1(float* acc, const uint32_t (*af)[4],
                                          const uint32_t* b) {
    #pragma unroll
    for (int kk = 0; kk < 8; ++kk)
        MMA(acc, af[kk][0], af[kk][1], af[kk][2], af[kk][3], b[2 * kk], b[2 * kk + 1]);
}

// ---------------------------------------------------------------------------
// Warp w: m-tile = w&3 (rows 16*(w&3)..+15), n-quarter = w>>2 (n8 groups
// 4*(w>>2) + {0..3} of the 8 groups in each 64-entry staged tile),
// processed SEQUENTIALLY with a single B fragment set.
// ---------------------------------------------------------------------------
__global__ __launch_bounds__(NTHR, 2)
void vq_mma_kernel(const float* __restrict__ ze,
                   const float* __restrict__ cb,
                   float* __restrict__ out,
                   int ntiles) {
    extern __shared__ __align__(16) char smem[];
    float* Cn = reinterpret_cast<float*>(smem + OFF_CN);

    const uint32_t sbase = smem_u32(smem);
    const int tid  = threadIdx.x;
    const int w    = tid >> 5;
    const int lane = tid & 31;

    // ---- 1. build A split tiles in smem (ldmatrix-packed, mma subtile order) ----
    {
        const float* zsrc = ze + (size_t)blockIdx.x * (BMW * D);
        for (int i = tid; i < BMW * D; i += NTHR) {
            const int m = i >> 7, k = i & 127;
            __half h1, h2;
            split2(zsrc[i], h1, h2);
            const int t = ((m >> 3) & 1) | (((k >> 3) & 1) << 1);
            const int base = (m >> 4) * 4096 + (k >> 4) * 512 + t * 128
                           + (m & 7) * 16 + (k & 7) * 2;
            *reinterpret_cast<__half*>(smem + base)         = h1;
            *reinterpret_cast<__half*>(smem + base + 16384) = h2;
        }
        for (int i = tid; i < ntiles * NTE; i += NTHR) Cn[i] = g_cnorm[i];
    }

    // ---- 2. prologue: stage B tile 0 (32KB) ----
    {
        const char* src = reinterpret_cast<const char*>(g_Bpk);
        #pragma unroll
        for (int u = 0; u < 8; ++u)
            cp_async16(sbase + OFF_B0 + u * 4096 + tid * 16, src + u * 4096 + tid * 16);
        asm volatile("cp.async.commit_group;");
    }
    __syncthreads();   // A tiles visible

    // ---- 3. both A split fragment sets resident in registers (m-tile = w&3) ----
    uint32_t a1f[8][4], a2f[8][4];
    const uint32_t abase = sbase + (w & 3) * 4096 + lane * 16;
    #pragma unroll
    for (int kk = 0; kk < 8; ++kk)
        LDSM4(a1f[kk][0], a1f[kk][1], a1f[kk][2], a1f[kk][3], abase + kk * 512);
    #pragma unroll
    for (int kk = 0; kk < 8; ++kk)
        LDSM4(a2f[kk][0], a2f[kk][1], a2f[kk][2], a2f[kk][3], abase + 16384 + kk * 512);

    float best[2] = {-CUDART_INF_F, -CUDART_INF_F};
    int   bidx[2] = {0, 0};

    for (int nt = 0; nt < ntiles; ++nt) {
        asm volatile("cp.async.wait_group 0;");
        __syncthreads();   // buf[nt&1] full for all; compute nt-1 done everywhere

        if (nt + 1 < ntiles) {
            const char* src = reinterpret_cast<const char*>(g_Bpk) + (size_t)(nt + 1) * 32768;
            const uint32_t dst = sbase + (((nt + 1) & 1) ? OFF_B1 : OFF_B0);
            #pragma unroll
            for (int u = 0; u < 8; ++u)
                cp_async16(dst + u * 4096 + tid * 16, src + u * 4096 + tid * 16);
            asm volatile("cp.async.commit_group;");
        }

        // per-lane base inside the current B buffer
        const uint32_t bb = sbase + ((nt & 1) ? OFF_B1 : OFF_B0) + lane * 16;
        const int ntbase = nt * NTE;

        #pragma unroll
        for (int g = 0; g < 4; ++g) {
            const int gi = (w >> 2) * 4 + g;              // n8 group index
            float accM[4] = {0.f, 0.f, 0.f, 0.f};
            float accR[4] = {0.f, 0.f, 0.f, 0.f};
            uint32_t br[16];

            // split s=0 of B (B1): passes (A1,B1)->accM, (A2',B1)->accR
            load_bfrags(br, bb + gi * 2048);
            mma_pass1(accM, a1f, br);
            mma_pass1(accR, a2f, br);

            // split s=1 of B (B2'): pass (A1,B2')->accR
            load_bfrags(br, bb + 16384 + gi * 2048);
            mma_pass1(accR, a1f, br);

            // ---- epilogue: score = accM + accR*2^-11 - cn, running argmax ----
            const int n0 = ntbase + gi * 8 + 2 * (lane & 3);
            const float2 cn2 = *reinterpret_cast<const float2*>(&Cn[n0]);
            const float s00 = fmaf(accR[0], RSCALE, accM[0]) - cn2.x;  // row g,   n0
            const float s01 = fmaf(accR[1], RSCALE, accM[1]) - cn2.y;  // row g,   n0+1
            const float s10 = fmaf(accR[2], RSCALE, accM[2]) - cn2.x;  // row g+8, n0
            const float s11 = fmaf(accR[3], RSCALE, accM[3]) - cn2.y;
            if (s00 > best[0]) { best[0] = s00; bidx[0] = n0; }
            if (s01 > best[0]) { best[0] = s01; bidx[0] = n0 + 1; }
            if (s10 > best[1]) { best[1] = s10; bidx[1] = n0; }
            if (s11 > best[1]) { best[1] = s11; bidx[1] = n0 + 1; }
        }
    }

    // ---- reduce 8 candidates per window (4 lane-quads x 2 n-quarters... cols) ----
    float* sF   = reinterpret_cast<float*>(smem + OFF_B0);         // [64][8]
    int*   sI   = reinterpret_cast<int*>(smem + OFF_B0 + 2048);
    int*   widx = reinterpret_cast<int*>(smem + OFF_B0 + 4096);
    __syncthreads();      // all warps done reading B buffers
    {
        const int m0  = 16 * (w & 3) + (lane >> 2);
        const int col = (w >> 2) * 4 + (lane & 3);
        sF[m0 * 8 + col] = best[0];        sI[m0 * 8 + col] = bidx[0];
        sF[(m0 + 8) * 8 + col] = best[1];  sI[(m0 + 8) * 8 + col] = bidx[1];
    }
    __syncthreads();
    if (tid < BMW) {
        float bs = sF[tid * 8];
        int   bi = sI[tid * 8];
        #pragma unroll
        for (int q = 1; q < 8; ++q) {
            const float s  = sF[tid * 8 + q];
            const int   ix = sI[tid * 8 + q];
            if (s > bs || (s == bs && ix < bi)) { bs = s; bi = ix; }
        }
        widx[tid] = bi;
    }
    __syncthreads();

    // ---- gather winning codebook rows (L2-hot) ----
    const float4* cb4  = reinterpret_cast<const float4*>(cb);
    float4*       out4 = reinterpret_cast<float4*>(out) + (size_t)blockIdx.x * (BMW * 32);
    #pragma unroll
    for (int i = 0; i < 8; ++i) {
        const int f = i * 256 + tid;          // 0..2047
        const int wv = f >> 5, c = f & 31;
        out4[f] = __ldg(&cb4[(size_t)widx[wv] * 32 + c]);
    }
}

// ---------------------------------------------------------------------------
extern "C" void kernel_launch(void* const* d_in, const int* in_sizes, int n_in,
                              void* d_out, int out_size) {
    const float* ze = (const float*)d_in[0];
    const float* cb = (const float*)d_in[1];
    float* out = (float*)d_out;

    const int M = in_sizes[0] / D;   // 65536
    const int K = in_sizes[1] / D;   // 2048

    cudaFuncSetAttribute(vq_mma_kernel, cudaFuncAttributeMaxDynamicSharedMemorySize,
                         SMEM_TOTAL);

    cnorm_kernel<<<(K + 7) / 8, NTHR>>>(cb, K);
    pack_cb_kernel<<<(K * D + NTHR - 1) / NTHR, NTHR>>>(cb, K);
    vq_mma_kernel<<<M / BMW, NTHR, SMEM_TOTAL>>>(ze, cb, out, K / NTE);
}